// round 2
// baseline (speedup 1.0000x reference)
#include <cuda_runtime.h>
#include <math.h>

#define NN      60000
#define IN_C    128
#define HID     512
#define D_CAT   1024
#define D_FC    2048
#define D_L1    4096
#define OUT_C   64
#define BN_EPS  1e-5f

// ---------------------------------------------------------------------------
// Scratch (no allocations allowed -> __device__ globals)
// ---------------------------------------------------------------------------
__device__ float g_h  [(size_t)NN * IN_C ];   // x + agg
__device__ float g_t  [(size_t)NN * HID  ];   // mm1 output (reused A then B)
__device__ float g_cat[(size_t)NN * D_CAT];   // [x1 | x2]
__device__ float g_fc [(size_t)NN * D_FC ];
__device__ float g_l1 [(size_t)NN * D_L1 ];
__device__ float g_l2 [(size_t)NN * D_FC ];

// ---------------------------------------------------------------------------
// init: g_h = x
// ---------------------------------------------------------------------------
__global__ void copy_x_kernel(const float4* __restrict__ x, float4* __restrict__ h, int n4) {
    int i = blockIdx.x * blockDim.x + threadIdx.x;
    if (i < n4) h[i] = x[i];
}

// ---------------------------------------------------------------------------
// edge aggregation: h[dst] += x[src]   (one warp per edge, float4 per lane)
// edge_index arrives as int32 (harness downcasts the reference's int64).
// ---------------------------------------------------------------------------
__global__ void edge_agg_kernel(const float* __restrict__ x,
                                const int* __restrict__ ei,
                                float* __restrict__ h, int n_edges) {
    int warp = (blockIdx.x * blockDim.x + threadIdx.x) >> 5;
    int lane = threadIdx.x & 31;
    if (warp >= n_edges) return;
    int src = ei[warp];
    int dst = ei[n_edges + warp];
    const float4 v = *reinterpret_cast<const float4*>(x + (size_t)src * IN_C + lane * 4);
    float* d = h + (size_t)dst * IN_C + lane * 4;
    atomicAdd(d + 0, v.x);
    atomicAdd(d + 1, v.y);
    atomicAdd(d + 2, v.z);
    atomicAdd(d + 3, v.w);
}

// ---------------------------------------------------------------------------
// SGEMM  C[M,N] = A[M,K] @ W[K,N]  (+bias, fused epilogue), row-major all.
// 128x128 block tile, 8x8 per-thread, BK=8, double buffered.
// ---------------------------------------------------------------------------
#define BM 128
#define BN 128
#define BK 8
#define TM 8
#define TN 8

#define EPI_NONE    0
#define EPI_RELU    1
#define EPI_BNRELU  2
#define EPI_LEAKY   3
#define EPI_SIGMOID 4

__global__ __launch_bounds__(256)
void sgemm_epi_kernel(const float* __restrict__ A, const float* __restrict__ B,
                      float* __restrict__ C, int M, int N, int K, int ldc,
                      const float* __restrict__ bias,
                      const float* __restrict__ gamma, const float* __restrict__ beta,
                      const float* __restrict__ mean,  const float* __restrict__ var,
                      int epi)
{
    __shared__ float As[2][BK][BM];
    __shared__ float Bs[2][BK][BN];

    const int tid = threadIdx.x;
    const int bx = blockIdx.x, by = blockIdx.y;
    const int tx = tid & 15, ty = tid >> 4;

    // A loader: one float4 per thread. row = tid>>1 (0..127), colseg = (tid&1)*4
    const int aRow = tid >> 1;
    const int aCol = (tid & 1) * 4;
    const int gARow = by * BM + aRow;
    const bool aValid = (gARow < M);
    const float* Aptr = A + (size_t)gARow * K + aCol;

    // B loader: one float4 per thread. row = tid>>5 (0..7), col = (tid&31)*4
    const int bRow = tid >> 5;
    const int bCol = (tid & 31) * 4;
    const int gBCol = bx * BN + bCol;
    const bool bValid = (gBCol < N);
    const float* Bptr = B + (size_t)bRow * N + gBCol;

    float acc[TM][TN];
#pragma unroll
    for (int i = 0; i < TM; i++)
#pragma unroll
        for (int j = 0; j < TN; j++) acc[i][j] = 0.0f;

    const float4 z4 = make_float4(0.f, 0.f, 0.f, 0.f);

    // prologue: tile 0 -> buf 0
    {
        float4 av = aValid ? *(const float4*)(Aptr) : z4;
        float4 bv = bValid ? *(const float4*)(Bptr) : z4;
        As[0][aCol + 0][aRow] = av.x;
        As[0][aCol + 1][aRow] = av.y;
        As[0][aCol + 2][aRow] = av.z;
        As[0][aCol + 3][aRow] = av.w;
        *(float4*)&Bs[0][bRow][bCol] = bv;
    }
    __syncthreads();

    const int nk = K / BK;
    int buf = 0;
    for (int t = 0; t < nk; t++) {
        float4 a_next = z4, b_next = z4;
        if (t + 1 < nk) {
            int k0 = (t + 1) * BK;
            if (aValid) a_next = *(const float4*)(Aptr + k0);
            if (bValid) b_next = *(const float4*)(Bptr + (size_t)k0 * N);
        }

#pragma unroll
        for (int k = 0; k < BK; k++) {
            float ar[TM], br[TN];
            *(float4*)&ar[0] = *(const float4*)&As[buf][k][ty * TM];
            *(float4*)&ar[4] = *(const float4*)&As[buf][k][ty * TM + 4];
            *(float4*)&br[0] = *(const float4*)&Bs[buf][k][tx * TN];
            *(float4*)&br[4] = *(const float4*)&Bs[buf][k][tx * TN + 4];
#pragma unroll
            for (int i = 0; i < TM; i++)
#pragma unroll
                for (int j = 0; j < TN; j++)
                    acc[i][j] = fmaf(ar[i], br[j], acc[i][j]);
        }

        if (t + 1 < nk) {
            int nb = buf ^ 1;
            As[nb][aCol + 0][aRow] = a_next.x;
            As[nb][aCol + 1][aRow] = a_next.y;
            As[nb][aCol + 2][aRow] = a_next.z;
            As[nb][aCol + 3][aRow] = a_next.w;
            *(float4*)&Bs[nb][bRow][bCol] = b_next;
        }
        __syncthreads();
        buf ^= 1;
    }

    // epilogue
    const int crow0 = by * BM + ty * TM;
    const int ccol0 = bx * BN + tx * TN;
#pragma unroll
    for (int i = 0; i < TM; i++) {
        int row = crow0 + i;
        if (row >= M) break;
#pragma unroll
        for (int jj = 0; jj < TN; jj += 4) {
            int col = ccol0 + jj;
            if (col >= N) continue;   // N is a multiple of 4; whole float4 in or out
            float4 v;
            float* vv = (float*)&v;
#pragma unroll
            for (int q = 0; q < 4; q++) {
                int c = col + q;
                float val = acc[i][jj + q] + bias[c];
                if (epi == EPI_BNRELU) {
                    val = (val - mean[c]) * rsqrtf(var[c] + BN_EPS) * gamma[c] + beta[c];
                    val = fmaxf(val, 0.0f);
                } else if (epi == EPI_RELU) {
                    val = fmaxf(val, 0.0f);
                } else if (epi == EPI_LEAKY) {
                    val = (val > 0.0f) ? val : 0.01f * val;
                } else if (epi == EPI_SIGMOID) {
                    val = 1.0f / (1.0f + expf(-val));
                }
                vv[q] = val;
            }
            *(float4*)(C + (size_t)row * ldc + col) = v;
        }
    }
}

// ---------------------------------------------------------------------------
// launch
// ---------------------------------------------------------------------------
static inline dim3 gemm_grid(int M, int N) {
    return dim3((N + BN - 1) / BN, (M + BM - 1) / BM);
}

extern "C" void kernel_launch(void* const* d_in, const int* in_sizes, int n_in,
                              void* d_out, int out_size) {
    const float* x   = (const float*)d_in[0];
    const int*   ei  = (const int*)d_in[1];     // int32 (harness-converted)
    const float *w1a = (const float*)d_in[2],  *b1a = (const float*)d_in[3];
    const float *ga  = (const float*)d_in[4],  *be_a = (const float*)d_in[5];
    const float *ma  = (const float*)d_in[6],  *va  = (const float*)d_in[7];
    const float *w2a = (const float*)d_in[8],  *b2a = (const float*)d_in[9];
    const float *w1b = (const float*)d_in[10], *b1b = (const float*)d_in[11];
    const float *gb  = (const float*)d_in[12], *be_b = (const float*)d_in[13];
    const float *mb  = (const float*)d_in[14], *vb  = (const float*)d_in[15];
    const float *w2b = (const float*)d_in[16], *b2b = (const float*)d_in[17];
    const float *fcw = (const float*)d_in[18], *fcb = (const float*)d_in[19];
    const float *l1w = (const float*)d_in[20], *l1b = (const float*)d_in[21];
    const float *l2w = (const float*)d_in[22], *l2b = (const float*)d_in[23];
    const float *ow  = (const float*)d_in[24], *ob  = (const float*)d_in[25];
    float* out = (float*)d_out;

    float *h, *t, *cat, *fc, *l1, *l2;
    cudaGetSymbolAddress((void**)&h,   g_h);
    cudaGetSymbolAddress((void**)&t,   g_t);
    cudaGetSymbolAddress((void**)&cat, g_cat);
    cudaGetSymbolAddress((void**)&fc,  g_fc);
    cudaGetSymbolAddress((void**)&l1,  g_l1);
    cudaGetSymbolAddress((void**)&l2,  g_l2);

    const int n_edges = in_sizes[1] / 2;

    // h = x
    {
        int n4 = NN * IN_C / 4;
        copy_x_kernel<<<(n4 + 255) / 256, 256>>>((const float4*)x, (float4*)h, n4);
    }
    // h += scatter-add of x[src] into dst
    {
        long long nthreads = (long long)n_edges * 32;
        int nblocks = (int)((nthreads + 255) / 256);
        edge_agg_kernel<<<nblocks, 256>>>(x, ei, h, n_edges);
    }

    // conv A
    sgemm_epi_kernel<<<gemm_grid(NN, HID), 256>>>(h, w1a, t,   NN, HID, IN_C, HID,
                                                  b1a, ga, be_a, ma, va, EPI_BNRELU);
    sgemm_epi_kernel<<<gemm_grid(NN, HID), 256>>>(t, w2a, cat, NN, HID, HID, D_CAT,
                                                  b2a, 0, 0, 0, 0, EPI_RELU);
    // conv B
    sgemm_epi_kernel<<<gemm_grid(NN, HID), 256>>>(h, w1b, t,   NN, HID, IN_C, HID,
                                                  b1b, gb, be_b, mb, vb, EPI_BNRELU);
    sgemm_epi_kernel<<<gemm_grid(NN, HID), 256>>>(t, w2b, cat + HID, NN, HID, HID, D_CAT,
                                                  b2b, 0, 0, 0, 0, EPI_RELU);
    // head
    sgemm_epi_kernel<<<gemm_grid(NN, D_FC), 256>>>(cat, fcw, fc, NN, D_FC, D_CAT, D_FC,
                                                   fcb, 0, 0, 0, 0, EPI_LEAKY);
    sgemm_epi_kernel<<<gemm_grid(NN, D_L1), 256>>>(fc, l1w, l1, NN, D_L1, D_FC, D_L1,
                                                   l1b, 0, 0, 0, 0, EPI_NONE);
    sgemm_epi_kernel<<<gemm_grid(NN, D_FC), 256>>>(l1, l2w, l2, NN, D_FC, D_L1, D_FC,
                                                   l2b, 0, 0, 0, 0, EPI_NONE);
    sgemm_epi_kernel<<<gemm_grid(NN, OUT_C), 256>>>(l2, ow, out, NN, OUT_C, D_FC, OUT_C,
                                                    ob, 0, 0, 0, 0, EPI_SIGMOID);
}

// round 4
// speedup vs baseline: 2.9639x; 2.9639x over previous
#include <cuda_runtime.h>
#include <cuda_bf16.h>
#include <math.h>
#include <stdint.h>

#define NN      60000
#define IN_C    128
#define HID     512
#define D_CAT   1024
#define D_FC    2048
#define D_L1    4096
#define OUT_C   64
#define BN_EPS  1e-5f

#define EPI_NONE    0
#define EPI_RELU    1
#define EPI_BNRELU  2
#define EPI_LEAKY   3
#define EPI_SIGMOID 4

typedef __nv_bfloat16 bf16;

// ---------------------------------------------------------------------------
// Scratch (__device__ globals; no allocations allowed)
// ---------------------------------------------------------------------------
__device__ float g_h[(size_t)NN * IN_C];              // x + agg (fp32, atomics)
__device__ bf16  g_h_hi [(size_t)NN * IN_C ],  g_h_lo [(size_t)NN * IN_C ];
__device__ bf16  g_t_hi [(size_t)NN * HID  ],  g_t_lo [(size_t)NN * HID  ];
__device__ bf16  g_c_hi [(size_t)NN * D_CAT],  g_c_lo [(size_t)NN * D_CAT];
__device__ bf16  g_fc_hi[(size_t)NN * D_FC ],  g_fc_lo[(size_t)NN * D_FC ];
__device__ bf16  g_l1_hi[(size_t)NN * D_L1 ],  g_l1_lo[(size_t)NN * D_L1 ];
__device__ bf16  g_l2_hi[(size_t)NN * D_FC ],  g_l2_lo[(size_t)NN * D_FC ];
// transposed weights [N,K] hi/lo
__device__ bf16 g_w1a_hi[HID * IN_C],   g_w1a_lo[HID * IN_C];
__device__ bf16 g_w2a_hi[HID * HID],    g_w2a_lo[HID * HID];
__device__ bf16 g_w1b_hi[HID * IN_C],   g_w1b_lo[HID * IN_C];
__device__ bf16 g_w2b_hi[HID * HID],    g_w2b_lo[HID * HID];
__device__ bf16 g_wfc_hi[D_FC * D_CAT], g_wfc_lo[D_FC * D_CAT];
__device__ bf16 g_wl1_hi[(size_t)D_L1 * D_FC], g_wl1_lo[(size_t)D_L1 * D_FC];
__device__ bf16 g_wl2_hi[(size_t)D_FC * D_L1], g_wl2_lo[(size_t)D_FC * D_L1];
__device__ bf16 g_wo_hi [OUT_C * D_FC], g_wo_lo [OUT_C * D_FC];

// ---------------------------------------------------------------------------
// helpers
// ---------------------------------------------------------------------------
__device__ __forceinline__ uint32_t smem_u32(const void* p) {
    uint32_t a;
    asm("{ .reg .u64 t; cvta.to.shared.u64 t, %1; cvt.u32.u64 %0, t; }" : "=r"(a) : "l"(p));
    return a;
}

#define LDSM4(r, a) \
    asm volatile("ldmatrix.sync.aligned.m8n8.x4.shared.b16 {%0,%1,%2,%3}, [%4];" \
        : "=r"((r)[0]), "=r"((r)[1]), "=r"((r)[2]), "=r"((r)[3]) : "r"(a))

#define MMA_BF16(d, a, b) \
    asm volatile("mma.sync.aligned.m16n8k16.row.col.f32.bf16.bf16.f32 " \
        "{%0,%1,%2,%3}, {%4,%5,%6,%7}, {%8,%9}, {%0,%1,%2,%3};" \
        : "+f"((d)[0]), "+f"((d)[1]), "+f"((d)[2]), "+f"((d)[3]) \
        : "r"((a)[0]), "r"((a)[1]), "r"((a)[2]), "r"((a)[3]), "r"((b)[0]), "r"((b)[1]))

#define CP_ASYNC(dst, src, ok) \
    asm volatile("cp.async.cg.shared.global [%0], [%1], 16, %2;" \
        :: "r"(dst), "l"(src), "r"(ok) : "memory")
#define CP_COMMIT()  asm volatile("cp.async.commit_group;" ::: "memory")
#define CP_WAIT1()   asm volatile("cp.async.wait_group 1;" ::: "memory")

// ---------------------------------------------------------------------------
// small kernels
// ---------------------------------------------------------------------------
__global__ void copy_x_kernel(const float4* __restrict__ x, float4* __restrict__ h, int n4) {
    int i = blockIdx.x * blockDim.x + threadIdx.x;
    if (i < n4) h[i] = x[i];
}

__global__ void edge_agg_kernel(const float* __restrict__ x, const int* __restrict__ ei,
                                float* __restrict__ h, int n_edges) {
    int warp = (blockIdx.x * blockDim.x + threadIdx.x) >> 5;
    int lane = threadIdx.x & 31;
    if (warp >= n_edges) return;
    int src = ei[warp];
    int dst = ei[n_edges + warp];
    const float4 v = *reinterpret_cast<const float4*>(x + (size_t)src * IN_C + lane * 4);
    float* d = h + (size_t)dst * IN_C + lane * 4;
    atomicAdd(d + 0, v.x); atomicAdd(d + 1, v.y);
    atomicAdd(d + 2, v.z); atomicAdd(d + 3, v.w);
}

__global__ void split_kernel(const float* __restrict__ in, bf16* __restrict__ hi,
                             bf16* __restrict__ lo, int n) {
    int i = blockIdx.x * blockDim.x + threadIdx.x;
    if (i >= n) return;
    float v = in[i];
    bf16 h = __float2bfloat16(v);
    hi[i] = h;
    lo[i] = __float2bfloat16(v - __bfloat162float(h));
}

// W[K,N] fp32 -> Wt[N,K] hi/lo bf16
__global__ void wtrans_kernel(const float* __restrict__ W, bf16* __restrict__ hi,
                              bf16* __restrict__ lo, int K, int N) {
    __shared__ float t[32][33];
    int n0 = blockIdx.x * 32, k0 = blockIdx.y * 32;
#pragma unroll
    for (int dy = 0; dy < 32; dy += 8) {
        int k = k0 + threadIdx.y + dy, n = n0 + threadIdx.x;
        t[threadIdx.y + dy][threadIdx.x] = (k < K && n < N) ? W[(size_t)k * N + n] : 0.f;
    }
    __syncthreads();
#pragma unroll
    for (int dy = 0; dy < 32; dy += 8) {
        int n = n0 + threadIdx.y + dy, k = k0 + threadIdx.x;
        if (n < N && k < K) {
            float v = t[threadIdx.x][threadIdx.y + dy];
            bf16 h = __float2bfloat16(v);
            hi[(size_t)n * K + k] = h;
            lo[(size_t)n * K + k] = __float2bfloat16(v - __bfloat162float(h));
        }
    }
}

// ---------------------------------------------------------------------------
// bf16x3 mma.sync GEMM: C[M,N] = A[M,K] @ Bt[N,K]^T
// BM=BN=128, BK=32, 256 threads (warp grid 4Mx2N, warp tile 32x64), 3 stages
// smem tile layout: rows of 64B (32 bf16), chunk swizzle c ^= (row>>1)&3
// ---------------------------------------------------------------------------
#define STAGES     3
#define TILE_BYTES 8192                 // 128 rows * 64 B
#define STAGE_B    (4 * TILE_BYTES)     // Ah, Al, Bh, Bl
#define SMEM_DYN   (STAGES * STAGE_B)   // 98304

__global__ __launch_bounds__(256)
void gemm_mma_kernel(const bf16* __restrict__ Ah, const bf16* __restrict__ Al,
                     const bf16* __restrict__ Bh, const bf16* __restrict__ Bl,
                     bf16* __restrict__ Ch, bf16* __restrict__ Cl,
                     float* __restrict__ Cf,
                     const float* __restrict__ bias,
                     const float* __restrict__ gamma, const float* __restrict__ beta,
                     const float* __restrict__ mean,  const float* __restrict__ var,
                     int M, int N, int K, int ldc, int epi)
{
    extern __shared__ __align__(128) char smem[];
    const uint32_t sb = smem_u32(smem);
    const int tid = threadIdx.x;
    const int lid = tid & 31, wid = tid >> 5;
    const int warpM = wid >> 1, warpN = wid & 1;
    const int m0 = blockIdx.y * 128, n0 = blockIdx.x * 128;
    const int NC = K >> 5;

    float acc[2][8][4];
#pragma unroll
    for (int i = 0; i < 2; i++)
#pragma unroll
        for (int j = 0; j < 8; j++)
#pragma unroll
            for (int q = 0; q < 4; q++) acc[i][j][q] = 0.0f;

    // ---- stage loader: 2048 16B-chunks / 256 threads = 8 per thread ----
    auto issue_stage = [&](int c, int s) {
        const int k0 = c << 5;
        const uint32_t stb = sb + s * STAGE_B;
#pragma unroll
        for (int q = 0; q < 8; q++) {
            int id = q * 256 + tid;
            int tile = id >> 9;            // 0:Ah 1:Al 2:Bh 3:Bl
            int idx = id & 511;
            int row = idx >> 2;
            int ch  = idx & 3;
            const bf16* base = (tile == 0) ? Ah : (tile == 1) ? Al
                             : (tile == 2) ? Bh : Bl;
            int r0   = (tile < 2) ? m0 : n0;
            int rmax = (tile < 2) ? M : N;
            int gr = r0 + row;
            unsigned ok = (gr < rmax) ? 16u : 0u;
            int rc = (gr < rmax) ? gr : 0;
            const char* src = (const char*)(base + (size_t)rc * K + k0) + ch * 16;
            uint32_t dst = stb + tile * TILE_BYTES + row * 64 +
                           ((ch ^ ((row >> 1) & 3)) << 4);
            CP_ASYNC(dst, src, ok);
        }
        CP_COMMIT();
    };

    issue_stage(0, 0);
    issue_stage(1, 1);

    const int grp = lid >> 3, lr = lid & 7;

    int s = 0;
    for (int c = 0; c < NC; c++) {
        CP_WAIT1();
        __syncthreads();
        if (c + 2 < NC) issue_stage(c + 2, (s + 2) % STAGES);
        else CP_COMMIT();

        const uint32_t stb = sb + s * STAGE_B;
#pragma unroll
        for (int ks = 0; ks < 2; ks++) {
            uint32_t ah[2][4], al[2][4];
#pragma unroll
            for (int i = 0; i < 2; i++) {
                int row = warpM * 32 + i * 16 + lr + ((grp & 1) << 3);
                int chk = 2 * ks + (grp >> 1);
                uint32_t ad = stb + row * 64 + ((chk ^ ((row >> 1) & 3)) << 4);
                LDSM4(ah[i], ad);
                LDSM4(al[i], ad + TILE_BYTES);
            }
            uint32_t bh[8][2], bl[8][2];
#pragma unroll
            for (int jj = 0; jj < 4; jj++) {
                int row = warpN * 64 + jj * 16 + lr + ((grp >= 2) ? 8 : 0);
                int chk = 2 * ks + (grp & 1);
                uint32_t bd = stb + 2 * TILE_BYTES + row * 64 +
                              ((chk ^ ((row >> 1) & 3)) << 4);
                uint32_t r[4];
                LDSM4(r, bd);
                bh[2 * jj][0] = r[0]; bh[2 * jj][1] = r[1];
                bh[2 * jj + 1][0] = r[2]; bh[2 * jj + 1][1] = r[3];
                LDSM4(r, bd + TILE_BYTES);
                bl[2 * jj][0] = r[0]; bl[2 * jj][1] = r[1];
                bl[2 * jj + 1][0] = r[2]; bl[2 * jj + 1][1] = r[3];
            }
#pragma unroll
            for (int i = 0; i < 2; i++)
#pragma unroll
                for (int j = 0; j < 8; j++) {
                    MMA_BF16(acc[i][j], ah[i], bh[j]);
                    MMA_BF16(acc[i][j], ah[i], bl[j]);
                    MMA_BF16(acc[i][j], al[i], bh[j]);
                }
        }
        s = (s + 1) % STAGES;
    }

    // ---- epilogue ----
    const int r_base = m0 + warpM * 32 + (lid >> 2);
    const int c_base = n0 + warpN * 64 + (lid & 3) * 2;
#pragma unroll
    for (int i = 0; i < 2; i++) {
#pragma unroll
        for (int half = 0; half < 2; half++) {
            int row = r_base + i * 16 + half * 8;
            if (row >= M) continue;
#pragma unroll
            for (int j = 0; j < 8; j++) {
                int col = c_base + j * 8;
                if (col >= N) continue;
                float v0 = acc[i][j][half * 2 + 0] + bias[col];
                float v1 = acc[i][j][half * 2 + 1] + bias[col + 1];
                if (epi == EPI_BNRELU) {
                    v0 = (v0 - mean[col])     * rsqrtf(var[col] + BN_EPS)     * gamma[col]     + beta[col];
                    v1 = (v1 - mean[col + 1]) * rsqrtf(var[col + 1] + BN_EPS) * gamma[col + 1] + beta[col + 1];
                    v0 = fmaxf(v0, 0.0f); v1 = fmaxf(v1, 0.0f);
                } else if (epi == EPI_RELU) {
                    v0 = fmaxf(v0, 0.0f); v1 = fmaxf(v1, 0.0f);
                } else if (epi == EPI_LEAKY) {
                    v0 = (v0 > 0.0f) ? v0 : 0.01f * v0;
                    v1 = (v1 > 0.0f) ? v1 : 0.01f * v1;
                }
                if (epi == EPI_SIGMOID) {
                    float2 o;
                    o.x = 1.0f / (1.0f + expf(-v0));
                    o.y = 1.0f / (1.0f + expf(-v1));
                    *(float2*)(Cf + (size_t)row * ldc + col) = o;
                } else {
                    bf16 h0 = __float2bfloat16(v0);
                    bf16 h1 = __float2bfloat16(v1);
                    *(__nv_bfloat162*)(Ch + (size_t)row * ldc + col) = __nv_bfloat162(h0, h1);
                    *(__nv_bfloat162*)(Cl + (size_t)row * ldc + col) = __nv_bfloat162(
                        __float2bfloat16(v0 - __bfloat162float(h0)),
                        __float2bfloat16(v1 - __bfloat162float(h1)));
                }
            }
        }
    }
}

// ---------------------------------------------------------------------------
// launch
// ---------------------------------------------------------------------------
static void launch_gemm(const bf16* Ah, const bf16* Al, const bf16* Bh, const bf16* Bl,
                        bf16* Ch, bf16* Cl, float* Cf, const float* bias,
                        const float* ga, const float* be, const float* me, const float* va,
                        int M, int N, int K, int ldc, int epi) {
    dim3 grid((N + 127) / 128, (M + 127) / 128);
    gemm_mma_kernel<<<grid, 256, SMEM_DYN>>>(Ah, Al, Bh, Bl, Ch, Cl, Cf, bias,
                                             ga, be, me, va, M, N, K, ldc, epi);
}

template <typename T> static T* sym(T* symbol) {
    void* p = nullptr;
    cudaGetSymbolAddress(&p, (const void*)symbol);
    return (T*)p;
}

extern "C" void kernel_launch(void* const* d_in, const int* in_sizes, int n_in,
                              void* d_out, int out_size) {
    const float* x  = (const float*)d_in[0];
    const int*   ei = (const int*)d_in[1];
    const float *w1a = (const float*)d_in[2],  *b1a = (const float*)d_in[3];
    const float *ga  = (const float*)d_in[4],  *bea = (const float*)d_in[5];
    const float *ma  = (const float*)d_in[6],  *va  = (const float*)d_in[7];
    const float *w2a = (const float*)d_in[8],  *b2a = (const float*)d_in[9];
    const float *w1b = (const float*)d_in[10], *b1b = (const float*)d_in[11];
    const float *gb  = (const float*)d_in[12], *beb = (const float*)d_in[13];
    const float *mb  = (const float*)d_in[14], *vb  = (const float*)d_in[15];
    const float *w2b = (const float*)d_in[16], *b2b = (const float*)d_in[17];
    const float *fcw = (const float*)d_in[18], *fcb = (const float*)d_in[19];
    const float *l1w = (const float*)d_in[20], *l1b = (const float*)d_in[21];
    const float *l2w = (const float*)d_in[22], *l2b = (const float*)d_in[23];
    const float *ow  = (const float*)d_in[24], *ob  = (const float*)d_in[25];
    float* out = (float*)d_out;

    cudaFuncSetAttribute(gemm_mma_kernel,
                         cudaFuncAttributeMaxDynamicSharedMemorySize, SMEM_DYN);

    float* h = sym(g_h);
    bf16 *hhi = sym(g_h_hi), *hlo = sym(g_h_lo);
    bf16 *thi = sym(g_t_hi), *tlo = sym(g_t_lo);
    bf16 *chi = sym(g_c_hi), *clo = sym(g_c_lo);
    bf16 *fhi = sym(g_fc_hi), *flo = sym(g_fc_lo);
    bf16 *l1hi = sym(g_l1_hi), *l1lo = sym(g_l1_lo);
    bf16 *l2hi = sym(g_l2_hi), *l2lo = sym(g_l2_lo);
    bf16 *w1ah = sym(g_w1a_hi), *w1al = sym(g_w1a_lo);
    bf16 *w2ah = sym(g_w2a_hi), *w2al = sym(g_w2a_lo);
    bf16 *w1bh = sym(g_w1b_hi), *w1bl = sym(g_w1b_lo);
    bf16 *w2bh = sym(g_w2b_hi), *w2bl = sym(g_w2b_lo);
    bf16 *wfh = sym(g_wfc_hi), *wfl = sym(g_wfc_lo);
    bf16 *wl1h = sym(g_wl1_hi), *wl1l = sym(g_wl1_lo);
    bf16 *wl2h = sym(g_wl2_hi), *wl2l = sym(g_wl2_lo);
    bf16 *woh = sym(g_wo_hi), *wol = sym(g_wo_lo);

    const int n_edges = in_sizes[1] / 2;

    // aggregation (fp32) + split
    {
        int n4 = NN * IN_C / 4;
        copy_x_kernel<<<(n4 + 255) / 256, 256>>>((const float4*)x, (float4*)h, n4);
        long long nthreads = (long long)n_edges * 32;
        edge_agg_kernel<<<(int)((nthreads + 255) / 256), 256>>>(x, ei, h, n_edges);
        int n = NN * IN_C;
        split_kernel<<<(n + 255) / 256, 256>>>(h, hhi, hlo, n);
    }
    // weight transpose + split
    {
        dim3 b(32, 8);
        wtrans_kernel<<<dim3(HID / 32,  IN_C / 32), b>>>(w1a, w1ah, w1al, IN_C, HID);
        wtrans_kernel<<<dim3(HID / 32,  HID / 32), b>>>(w2a, w2ah, w2al, HID, HID);
        wtrans_kernel<<<dim3(HID / 32,  IN_C / 32), b>>>(w1b, w1bh, w1bl, IN_C, HID);
        wtrans_kernel<<<dim3(HID / 32,  HID / 32), b>>>(w2b, w2bh, w2bl, HID, HID);
        wtrans_kernel<<<dim3(D_FC / 32, D_CAT / 32), b>>>(fcw, wfh, wfl, D_CAT, D_FC);
        wtrans_kernel<<<dim3(D_L1 / 32, D_FC / 32), b>>>(l1w, wl1h, wl1l, D_FC, D_L1);
        wtrans_kernel<<<dim3(D_FC / 32, D_L1 / 32), b>>>(l2w, wl2h, wl2l, D_L1, D_FC);
        wtrans_kernel<<<dim3(OUT_C / 32, D_FC / 32), b>>>(ow, woh, wol, D_FC, OUT_C);
    }

    // conv A
    launch_gemm(hhi, hlo, w1ah, w1al, thi, tlo, 0, b1a, ga, bea, ma, va,
                NN, HID, IN_C, HID, EPI_BNRELU);
    launch_gemm(thi, tlo, w2ah, w2al, chi, clo, 0, b2a, 0, 0, 0, 0,
                NN, HID, HID, D_CAT, EPI_RELU);
    // conv B
    launch_gemm(hhi, hlo, w1bh, w1bl, thi, tlo, 0, b1b, gb, beb, mb, vb,
                NN, HID, IN_C, HID, EPI_BNRELU);
    launch_gemm(thi, tlo, w2bh, w2bl, chi + HID, clo + HID, 0, b2b, 0, 0, 0, 0,
                NN, HID, HID, D_CAT, EPI_RELU);
    // head
    launch_gemm(chi, clo, wfh, wfl, fhi, flo, 0, fcb, 0, 0, 0, 0,
                NN, D_FC, D_CAT, D_FC, EPI_LEAKY);
    launch_gemm(fhi, flo, wl1h, wl1l, l1hi, l1lo, 0, l1b, 0, 0, 0, 0,
                NN, D_L1, D_FC, D_L1, EPI_NONE);
    launch_gemm(l1hi, l1lo, wl2h, wl2l, l2hi, l2lo, 0, l2b, 0, 0, 0, 0,
                NN, D_FC, D_L1, D_FC, EPI_NONE);
    launch_gemm(l2hi, l2lo, woh, wol, 0, 0, out, ob, 0, 0, 0, 0,
                NN, OUT_C, D_FC, OUT_C, EPI_SIGMOID);
}

// round 5
// speedup vs baseline: 3.2842x; 1.1081x over previous
#include <cuda_runtime.h>
#include <cuda_bf16.h>
#include <math.h>
#include <stdint.h>

#define NN      60000
#define IN_C    128
#define HID     512
#define D_CAT   1024
#define D_FC    2048
#define D_L1    4096
#define OUT_C   64
#define BN_EPS  1e-5f

#define EPI_NONE    0
#define EPI_RELU    1
#define EPI_BNRELU  2
#define EPI_LEAKY   3
#define EPI_SIGMOID 4

typedef __nv_bfloat16 bf16;

// ---------------------------------------------------------------------------
// Scratch (__device__ globals; no allocations allowed)
// ---------------------------------------------------------------------------
__device__ float g_h[(size_t)NN * IN_C];              // x + agg (fp32, atomics)
__device__ bf16  g_h_hi [(size_t)NN * IN_C ],  g_h_lo [(size_t)NN * IN_C ];
__device__ bf16  g_t_hi [(size_t)NN * HID  ],  g_t_lo [(size_t)NN * HID  ];
__device__ bf16  g_c_hi [(size_t)NN * D_CAT],  g_c_lo [(size_t)NN * D_CAT];
__device__ bf16  g_fc_hi[(size_t)NN * D_FC ],  g_fc_lo[(size_t)NN * D_FC ];
__device__ bf16  g_l1_hi[(size_t)NN * D_L1 ],  g_l1_lo[(size_t)NN * D_L1 ];
__device__ bf16  g_l2_hi[(size_t)NN * D_FC ],  g_l2_lo[(size_t)NN * D_FC ];
// transposed weights [N,K] hi/lo
__device__ bf16 g_w1a_hi[HID * IN_C],   g_w1a_lo[HID * IN_C];
__device__ bf16 g_w2a_hi[HID * HID],    g_w2a_lo[HID * HID];
__device__ bf16 g_w1b_hi[HID * IN_C],   g_w1b_lo[HID * IN_C];
__device__ bf16 g_w2b_hi[HID * HID],    g_w2b_lo[HID * HID];
__device__ bf16 g_wfc_hi[D_FC * D_CAT], g_wfc_lo[D_FC * D_CAT];
__device__ bf16 g_wl1_hi[(size_t)D_L1 * D_FC], g_wl1_lo[(size_t)D_L1 * D_FC];
__device__ bf16 g_wl2_hi[(size_t)D_FC * D_L1], g_wl2_lo[(size_t)D_FC * D_L1];
__device__ bf16 g_wo_hi [OUT_C * D_FC], g_wo_lo [OUT_C * D_FC];

// ---------------------------------------------------------------------------
// helpers
// ---------------------------------------------------------------------------
__device__ __forceinline__ uint32_t smem_u32(const void* p) {
    uint32_t a;
    asm("{ .reg .u64 t; cvta.to.shared.u64 t, %1; cvt.u32.u64 %0, t; }" : "=r"(a) : "l"(p));
    return a;
}

#define LDSM4(r, a) \
    asm volatile("ldmatrix.sync.aligned.m8n8.x4.shared.b16 {%0,%1,%2,%3}, [%4];" \
        : "=r"((r)[0]), "=r"((r)[1]), "=r"((r)[2]), "=r"((r)[3]) : "r"(a))

#define MMA_BF16(d, a, b) \
    asm volatile("mma.sync.aligned.m16n8k16.row.col.f32.bf16.bf16.f32 " \
        "{%0,%1,%2,%3}, {%4,%5,%6,%7}, {%8,%9}, {%0,%1,%2,%3};" \
        : "+f"((d)[0]), "+f"((d)[1]), "+f"((d)[2]), "+f"((d)[3]) \
        : "r"((a)[0]), "r"((a)[1]), "r"((a)[2]), "r"((a)[3]), "r"((b)[0]), "r"((b)[1]))

#define CP_ASYNC(dst, src, ok) \
    asm volatile("cp.async.cg.shared.global [%0], [%1], 16, %2;" \
        :: "r"(dst), "l"(src), "r"(ok) : "memory")
#define CP_COMMIT()  asm volatile("cp.async.commit_group;" ::: "memory")
#define CP_WAIT2()   asm volatile("cp.async.wait_group 2;" ::: "memory")

// ---------------------------------------------------------------------------
// small kernels
// ---------------------------------------------------------------------------
__global__ void copy_x_kernel(const float4* __restrict__ x, float4* __restrict__ h, int n4) {
    int i = blockIdx.x * blockDim.x + threadIdx.x;
    if (i < n4) h[i] = x[i];
}

__global__ void edge_agg_kernel(const float* __restrict__ x, const int* __restrict__ ei,
                                float* __restrict__ h, int n_edges) {
    int warp = (blockIdx.x * blockDim.x + threadIdx.x) >> 5;
    int lane = threadIdx.x & 31;
    if (warp >= n_edges) return;
    int src = ei[warp];
    int dst = ei[n_edges + warp];
    const float4 v = *reinterpret_cast<const float4*>(x + (size_t)src * IN_C + lane * 4);
    float* d = h + (size_t)dst * IN_C + lane * 4;
    atomicAdd(d + 0, v.x); atomicAdd(d + 1, v.y);
    atomicAdd(d + 2, v.z); atomicAdd(d + 3, v.w);
}

__global__ void split_kernel(const float* __restrict__ in, bf16* __restrict__ hi,
                             bf16* __restrict__ lo, int n) {
    int i = blockIdx.x * blockDim.x + threadIdx.x;
    if (i >= n) return;
    float v = in[i];
    bf16 h = __float2bfloat16(v);
    hi[i] = h;
    lo[i] = __float2bfloat16(v - __bfloat162float(h));
}

// W[K,N] fp32 -> Wt[N,K] hi/lo bf16
__global__ void wtrans_kernel(const float* __restrict__ W, bf16* __restrict__ hi,
                              bf16* __restrict__ lo, int K, int N) {
    __shared__ float t[32][33];
    int n0 = blockIdx.x * 32, k0 = blockIdx.y * 32;
#pragma unroll
    for (int dy = 0; dy < 32; dy += 8) {
        int k = k0 + threadIdx.y + dy, n = n0 + threadIdx.x;
        t[threadIdx.y + dy][threadIdx.x] = (k < K && n < N) ? W[(size_t)k * N + n] : 0.f;
    }
    __syncthreads();
#pragma unroll
    for (int dy = 0; dy < 32; dy += 8) {
        int n = n0 + threadIdx.y + dy, k = k0 + threadIdx.x;
        if (n < N && k < K) {
            float v = t[threadIdx.x][threadIdx.y + dy];
            bf16 h = __float2bfloat16(v);
            hi[(size_t)n * K + k] = h;
            lo[(size_t)n * K + k] = __float2bfloat16(v - __bfloat162float(h));
        }
    }
}

// ---------------------------------------------------------------------------
// bf16x3 mma.sync GEMM: C[M,N] = A[M,K] @ Bt[N,K]^T
// BM=256, BN=128, BK=32, 256 threads (warp grid 4Mx2N, warp tile 64x64), 4 stages
// smem tile layout: rows of 64B (32 bf16), chunk swizzle c ^= (row>>1)&3
// ---------------------------------------------------------------------------
#define STAGES    4
#define A_BYTES   16384             // 256 rows * 64 B
#define B_BYTES   8192              // 128 rows * 64 B
#define STAGE_B   (2 * A_BYTES + 2 * B_BYTES)   // Ah, Al, Bh, Bl = 49152
#define OFF_AL    16384
#define OFF_BH    32768
#define OFF_BL    40960
#define SMEM_DYN  (STAGES * STAGE_B)            // 196608

__global__ __launch_bounds__(256)
void gemm_mma_kernel(const bf16* __restrict__ Ah_g, const bf16* __restrict__ Al_g,
                     const bf16* __restrict__ Bh_g, const bf16* __restrict__ Bl_g,
                     bf16* __restrict__ Ch, bf16* __restrict__ Cl,
                     float* __restrict__ Cf,
                     const float* __restrict__ bias,
                     const float* __restrict__ gamma, const float* __restrict__ beta,
                     const float* __restrict__ mean,  const float* __restrict__ var,
                     int M, int N, int K, int ldc, int epi)
{
    extern __shared__ __align__(128) char smem[];
    const uint32_t sb = smem_u32(smem);
    const int tid = threadIdx.x;
    const int lid = tid & 31, wid = tid >> 5;
    const int warpM = wid >> 1, warpN = wid & 1;
    const int m0 = blockIdx.y * 256, n0 = blockIdx.x * 128;
    const int NC = K >> 5;

    float acc[4][8][4];
#pragma unroll
    for (int i = 0; i < 4; i++)
#pragma unroll
        for (int j = 0; j < 8; j++)
#pragma unroll
            for (int q = 0; q < 4; q++) acc[i][j][q] = 0.0f;

    // ---- stage loader: 3072 16B-chunks / 256 threads = 12 per thread ----
    auto issue_stage = [&](int c, int s) {
        const int k0 = c << 5;
        const uint32_t stb = sb + s * STAGE_B;
#pragma unroll
        for (int q = 0; q < 12; q++) {
            int id = q * 256 + tid;
            const bf16* base;
            uint32_t toff;
            int row, ch, gr, rmax;
            if (id < 2048) {                  // A: hi then lo, 256 rows x 4 chunks
                int half = id >> 10;
                int idx = id & 1023;
                row = idx >> 2; ch = idx & 3;
                base = half ? Al_g : Ah_g;
                toff = half ? OFF_AL : 0u;
                gr = m0 + row; rmax = M;
            } else {                          // B: hi then lo, 128 rows x 4 chunks
                int idB = id - 2048;
                int half = idB >> 9;
                int idx = idB & 511;
                row = idx >> 2; ch = idx & 3;
                base = half ? Bl_g : Bh_g;
                toff = half ? (uint32_t)OFF_BL : (uint32_t)OFF_BH;
                gr = n0 + row; rmax = N;
            }
            unsigned ok = (gr < rmax) ? 16u : 0u;
            int rc = (gr < rmax) ? gr : 0;
            const char* src = (const char*)(base + (size_t)rc * K + k0) + ch * 16;
            uint32_t dst = stb + toff + row * 64 + ((ch ^ ((row >> 1) & 3)) << 4);
            CP_ASYNC(dst, src, ok);
        }
        CP_COMMIT();
    };

    issue_stage(0, 0);
    issue_stage(1, 1);
    issue_stage(2, 2);

    const int grp = lid >> 3, lr = lid & 7;

    int s = 0;
    for (int c = 0; c < NC; c++) {
        CP_WAIT2();
        __syncthreads();
        if (c + 3 < NC) issue_stage(c + 3, (s + 3) & 3);
        else CP_COMMIT();

        const uint32_t stb = sb + s * STAGE_B;
#pragma unroll
        for (int ks = 0; ks < 2; ks++) {
            uint32_t ah[4][4], al[4][4];
#pragma unroll
            for (int i = 0; i < 4; i++) {
                int row = warpM * 64 + i * 16 + lr + ((grp & 1) << 3);
                int chk = 2 * ks + (grp >> 1);
                uint32_t ad = stb + row * 64 + ((chk ^ ((row >> 1) & 3)) << 4);
                LDSM4(ah[i], ad);
                LDSM4(al[i], ad + OFF_AL);
            }
            uint32_t bh[8][2], bl[8][2];
#pragma unroll
            for (int jj = 0; jj < 4; jj++) {
                int row = warpN * 64 + jj * 16 + lr + ((grp >= 2) ? 8 : 0);
                int chk = 2 * ks + (grp & 1);
                uint32_t bd = stb + OFF_BH + row * 64 + ((chk ^ ((row >> 1) & 3)) << 4);
                uint32_t r[4];
                LDSM4(r, bd);
                bh[2 * jj][0] = r[0]; bh[2 * jj][1] = r[1];
                bh[2 * jj + 1][0] = r[2]; bh[2 * jj + 1][1] = r[3];
                LDSM4(r, bd + (OFF_BL - OFF_BH));
                bl[2 * jj][0] = r[0]; bl[2 * jj][1] = r[1];
                bl[2 * jj + 1][0] = r[2]; bl[2 * jj + 1][1] = r[3];
            }
#pragma unroll
            for (int i = 0; i < 4; i++)
#pragma unroll
                for (int j = 0; j < 8; j++) {
                    MMA_BF16(acc[i][j], ah[i], bh[j]);
                    MMA_BF16(acc[i][j], ah[i], bl[j]);
                    MMA_BF16(acc[i][j], al[i], bh[j]);
                }
        }
        s = (s + 1) & 3;
    }

    // ---- epilogue ----
    const int r_base = m0 + warpM * 64 + (lid >> 2);
    const int c_base = n0 + warpN * 64 + (lid & 3) * 2;
#pragma unroll
    for (int i = 0; i < 4; i++) {
#pragma unroll
        for (int half = 0; half < 2; half++) {
            int row = r_base + i * 16 + half * 8;
            if (row >= M) continue;
#pragma unroll
            for (int j = 0; j < 8; j++) {
                int col = c_base + j * 8;
                if (col >= N) continue;
                float v0 = acc[i][j][half * 2 + 0] + bias[col];
                float v1 = acc[i][j][half * 2 + 1] + bias[col + 1];
                if (epi == EPI_BNRELU) {
                    v0 = (v0 - mean[col])     * rsqrtf(var[col] + BN_EPS)     * gamma[col]     + beta[col];
                    v1 = (v1 - mean[col + 1]) * rsqrtf(var[col + 1] + BN_EPS) * gamma[col + 1] + beta[col + 1];
                    v0 = fmaxf(v0, 0.0f); v1 = fmaxf(v1, 0.0f);
                } else if (epi == EPI_RELU) {
                    v0 = fmaxf(v0, 0.0f); v1 = fmaxf(v1, 0.0f);
                } else if (epi == EPI_LEAKY) {
                    v0 = (v0 > 0.0f) ? v0 : 0.01f * v0;
                    v1 = (v1 > 0.0f) ? v1 : 0.01f * v1;
                }
                if (epi == EPI_SIGMOID) {
                    float2 o;
                    o.x = 1.0f / (1.0f + expf(-v0));
                    o.y = 1.0f / (1.0f + expf(-v1));
                    *(float2*)(Cf + (size_t)row * ldc + col) = o;
                } else {
                    bf16 h0 = __float2bfloat16(v0);
                    bf16 h1 = __float2bfloat16(v1);
                    *(__nv_bfloat162*)(Ch + (size_t)row * ldc + col) = __nv_bfloat162(h0, h1);
                    *(__nv_bfloat162*)(Cl + (size_t)row * ldc + col) = __nv_bfloat162(
                        __float2bfloat16(v0 - __bfloat162float(h0)),
                        __float2bfloat16(v1 - __bfloat162float(h1)));
                }
            }
        }
    }
}

// ---------------------------------------------------------------------------
// launch
// ---------------------------------------------------------------------------
static void launch_gemm(const bf16* Ah, const bf16* Al, const bf16* Bh, const bf16* Bl,
                        bf16* Ch, bf16* Cl, float* Cf, const float* bias,
                        const float* ga, const float* be, const float* me, const float* va,
                        int M, int N, int K, int ldc, int epi) {
    dim3 grid((N + 127) / 128, (M + 255) / 256);
    gemm_mma_kernel<<<grid, 256, SMEM_DYN>>>(Ah, Al, Bh, Bl, Ch, Cl, Cf, bias,
                                             ga, be, me, va, M, N, K, ldc, epi);
}

template <typename T> static T* sym(T* symbol) {
    void* p = nullptr;
    cudaGetSymbolAddress(&p, (const void*)symbol);
    return (T*)p;
}

extern "C" void kernel_launch(void* const* d_in, const int* in_sizes, int n_in,
                              void* d_out, int out_size) {
    const float* x  = (const float*)d_in[0];
    const int*   ei = (const int*)d_in[1];
    const float *w1a = (const float*)d_in[2],  *b1a = (const float*)d_in[3];
    const float *ga  = (const float*)d_in[4],  *bea = (const float*)d_in[5];
    const float *ma  = (const float*)d_in[6],  *va  = (const float*)d_in[7];
    const float *w2a = (const float*)d_in[8],  *b2a = (const float*)d_in[9];
    const float *w1b = (const float*)d_in[10], *b1b = (const float*)d_in[11];
    const float *gb  = (const float*)d_in[12], *beb = (const float*)d_in[13];
    const float *mb  = (const float*)d_in[14], *vb  = (const float*)d_in[15];
    const float *w2b = (const float*)d_in[16], *b2b = (const float*)d_in[17];
    const float *fcw = (const float*)d_in[18], *fcb = (const float*)d_in[19];
    const float *l1w = (const float*)d_in[20], *l1b = (const float*)d_in[21];
    const float *l2w = (const float*)d_in[22], *l2b = (const float*)d_in[23];
    const float *ow  = (const float*)d_in[24], *ob  = (const float*)d_in[25];
    float* out = (float*)d_out;

    cudaFuncSetAttribute(gemm_mma_kernel,
                         cudaFuncAttributeMaxDynamicSharedMemorySize, SMEM_DYN);

    float* h = sym(g_h);
    bf16 *hhi = sym(g_h_hi), *hlo = sym(g_h_lo);
    bf16 *thi = sym(g_t_hi), *tlo = sym(g_t_lo);
    bf16 *chi = sym(g_c_hi), *clo = sym(g_c_lo);
    bf16 *fhi = sym(g_fc_hi), *flo = sym(g_fc_lo);
    bf16 *l1hi = sym(g_l1_hi), *l1lo = sym(g_l1_lo);
    bf16 *l2hi = sym(g_l2_hi), *l2lo = sym(g_l2_lo);
    bf16 *w1ah = sym(g_w1a_hi), *w1al = sym(g_w1a_lo);
    bf16 *w2ah = sym(g_w2a_hi), *w2al = sym(g_w2a_lo);
    bf16 *w1bh = sym(g_w1b_hi), *w1bl = sym(g_w1b_lo);
    bf16 *w2bh = sym(g_w2b_hi), *w2bl = sym(g_w2b_lo);
    bf16 *wfh = sym(g_wfc_hi), *wfl = sym(g_wfc_lo);
    bf16 *wl1h = sym(g_wl1_hi), *wl1l = sym(g_wl1_lo);
    bf16 *wl2h = sym(g_wl2_hi), *wl2l = sym(g_wl2_lo);
    bf16 *woh = sym(g_wo_hi), *wol = sym(g_wo_lo);

    const int n_edges = in_sizes[1] / 2;

    // aggregation (fp32) + split
    {
        int n4 = NN * IN_C / 4;
        copy_x_kernel<<<(n4 + 255) / 256, 256>>>((const float4*)x, (float4*)h, n4);
        long long nthreads = (long long)n_edges * 32;
        edge_agg_kernel<<<(int)((nthreads + 255) / 256), 256>>>(x, ei, h, n_edges);
        int n = NN * IN_C;
        split_kernel<<<(n + 255) / 256, 256>>>(h, hhi, hlo, n);
    }
    // weight transpose + split
    {
        dim3 b(32, 8);
        wtrans_kernel<<<dim3(HID / 32,  IN_C / 32), b>>>(w1a, w1ah, w1al, IN_C, HID);
        wtrans_kernel<<<dim3(HID / 32,  HID / 32), b>>>(w2a, w2ah, w2al, HID, HID);
        wtrans_kernel<<<dim3(HID / 32,  IN_C / 32), b>>>(w1b, w1bh, w1bl, IN_C, HID);
        wtrans_kernel<<<dim3(HID / 32,  HID / 32), b>>>(w2b, w2bh, w2bl, HID, HID);
        wtrans_kernel<<<dim3(D_FC / 32, D_CAT / 32), b>>>(fcw, wfh, wfl, D_CAT, D_FC);
        wtrans_kernel<<<dim3(D_L1 / 32, D_FC / 32), b>>>(l1w, wl1h, wl1l, D_FC, D_L1);
        wtrans_kernel<<<dim3(D_FC / 32, D_L1 / 32), b>>>(l2w, wl2h, wl2l, D_L1, D_FC);
        wtrans_kernel<<<dim3(OUT_C / 32, D_FC / 32), b>>>(ow, woh, wol, D_FC, OUT_C);
    }

    // conv A
    launch_gemm(hhi, hlo, w1ah, w1al, thi, tlo, 0, b1a, ga, bea, ma, va,
                NN, HID, IN_C, HID, EPI_BNRELU);
    launch_gemm(thi, tlo, w2ah, w2al, chi, clo, 0, b2a, 0, 0, 0, 0,
                NN, HID, HID, D_CAT, EPI_RELU);
    // conv B
    launch_gemm(hhi, hlo, w1bh, w1bl, thi, tlo, 0, b1b, gb, beb, mb, vb,
                NN, HID, IN_C, HID, EPI_BNRELU);
    launch_gemm(thi, tlo, w2bh, w2bl, chi + HID, clo + HID, 0, b2b, 0, 0, 0, 0,
                NN, HID, HID, D_CAT, EPI_RELU);
    // head
    launch_gemm(chi, clo, wfh, wfl, fhi, flo, 0, fcb, 0, 0, 0, 0,
                NN, D_FC, D_CAT, D_FC, EPI_LEAKY);
    launch_gemm(fhi, flo, wl1h, wl1l, l1hi, l1lo, 0, l1b, 0, 0, 0, 0,
                NN, D_L1, D_FC, D_L1, EPI_NONE);
    launch_gemm(l1hi, l1lo, wl2h, wl2l, l2hi, l2lo, 0, l2b, 0, 0, 0, 0,
                NN, D_FC, D_L1, D_FC, EPI_NONE);
    launch_gemm(l2hi, l2lo, woh, wol, 0, 0, out, ob, 0, 0, 0, 0,
                NN, OUT_C, D_FC, OUT_C, EPI_SIGMOID);
}